// round 17
// baseline (speedup 1.0000x reference)
#include <cuda_runtime.h>
#include <cuda_bf16.h>
#include <cuda_fp16.h>

#define NSP 4096
#define CDIM 256
#define NB 8
#define BQ 64
#define BK 32
#define NK (NSP / BK)
#define LOG2E 1.4426950408889634f

// ---- scratch ----
__device__ __align__(256) __half g_Qh[(size_t)NB * NSP * CDIM];   // [b][n][c] fp16 (xLOG2E)
__device__ __align__(256) __half g_Kh[(size_t)NB * NSP * CDIM];   // [b][n][c] fp16
__device__ __align__(256) __half g_Vh[(size_t)NB * CDIM * NSP];   // [b][c][n] fp16
__device__ __align__(256) __nv_bfloat16 g_Xx1[(size_t)NB * NSP * CDIM];
__device__ __align__(256) __nv_bfloat16 g_Xx2[(size_t)NB * NSP * CDIM];
__device__ __align__(256) __nv_bfloat16 g_Xa1[(size_t)NB * NSP * CDIM];
__device__ __align__(256) __nv_bfloat16 g_Xa2[(size_t)NB * NSP * CDIM];
__device__ __align__(256) __nv_bfloat16 g_W1[3][65536];
__device__ __align__(256) __nv_bfloat16 g_W2[3][65536];

typedef unsigned long long u64;
typedef unsigned int u32;
typedef unsigned short u16;

// ================= helpers =================
__device__ __forceinline__ u32 smem_u32(const void* p) {
    u32 a;
    asm("{ .reg .u64 t; cvta.to.shared.u64 t, %1; cvt.u32.u64 %0, t; }" : "=r"(a) : "l"(p));
    return a;
}
__device__ __forceinline__ float ex2f(float x) {
    float y; asm("ex2.approx.f32 %0, %1;" : "=f"(y) : "f"(x)); return y;
}
__device__ __forceinline__ void ldsm4(u32* r, u32 addr) {
    asm volatile("ldmatrix.sync.aligned.m8n8.x4.shared.b16 {%0,%1,%2,%3}, [%4];"
                 : "=r"(r[0]), "=r"(r[1]), "=r"(r[2]), "=r"(r[3]) : "r"(addr));
}
__device__ __forceinline__ void mma_bf16(float* d, const u32* a, u32 b0, u32 b1) {
    asm volatile(
        "mma.sync.aligned.m16n8k16.row.col.f32.bf16.bf16.f32 "
        "{%0,%1,%2,%3}, {%4,%5,%6,%7}, {%8,%9}, {%0,%1,%2,%3};"
        : "+f"(d[0]), "+f"(d[1]), "+f"(d[2]), "+f"(d[3])
        : "r"(a[0]), "r"(a[1]), "r"(a[2]), "r"(a[3]), "r"(b0), "r"(b1));
}
__device__ __forceinline__ void mma_f16(float* d, const u32* a, u32 b0, u32 b1) {
    asm volatile(
        "mma.sync.aligned.m16n8k16.row.col.f32.f16.f16.f32 "
        "{%0,%1,%2,%3}, {%4,%5,%6,%7}, {%8,%9}, {%0,%1,%2,%3};"
        : "+f"(d[0]), "+f"(d[1]), "+f"(d[2]), "+f"(d[3])
        : "r"(a[0]), "r"(a[1]), "r"(a[2]), "r"(a[3]), "r"(b0), "r"(b1));
}
__device__ __forceinline__ u32 lds_u32(u32 a) {
    u32 v; asm volatile("ld.shared.b32 %0, [%1];" : "=r"(v) : "r"(a)); return v;
}
__device__ __forceinline__ float lds_f32(u32 a) {
    float v; asm volatile("ld.shared.f32 %0, [%1];" : "=f"(v) : "r"(a)); return v;
}
__device__ __forceinline__ void sts_u32(u32 a, u32 v) {
    asm volatile("st.shared.b32 [%0], %1;" :: "r"(a), "r"(v) : "memory");
}
__device__ __forceinline__ void sts_f32(u32 a, float v) {
    asm volatile("st.shared.f32 [%0], %1;" :: "r"(a), "f"(v) : "memory");
}
__device__ __forceinline__ void sts_v2f(u32 a, float x, float y) {
    asm volatile("st.shared.v2.f32 [%0], {%1,%2};" :: "r"(a), "f"(x), "f"(y) : "memory");
}
__device__ __forceinline__ void sts_v4(u32 a, uint4 v) {
    asm volatile("st.shared.v4.b32 [%0], {%1,%2,%3,%4};"
                 :: "r"(a), "r"(v.x), "r"(v.y), "r"(v.z), "r"(v.w) : "memory");
}
#define CP16(dst, src) asm volatile("cp.async.cg.shared.global [%0], [%1], 16;" \
    :: "r"(dst), "l"(src) : "memory")
#define CPCOMMIT() asm volatile("cp.async.commit_group;" ::: "memory")
#define CPWAIT(n)  asm volatile("cp.async.wait_group %0;" :: "n"(n) : "memory")
#define BAR_SYNC(id, cnt) asm volatile("bar.sync %0, %1;" :: "r"(id), "r"(cnt) : "memory")

__device__ __forceinline__ void bfsplit(float f, u16& hi, u16& lo) {
    __nv_bfloat16 h = __float2bfloat16_rn(f);
    __nv_bfloat16 l = __float2bfloat16_rn(f - __bfloat162float(h));
    hi = __bfloat16_as_ushort(h);
    lo = __bfloat16_as_ushort(l);
}
__device__ __forceinline__ u32 packh2(float a, float b) {
    __half h0 = __float2half_rn(a);
    __half h1 = __float2half_rn(b);
    return (u32)__half_as_ushort(h0) | ((u32)__half_as_ushort(h1) << 16);
}

// ---------------------------------------------------------------------------
// Kernel A: split weights into bf16 hi/lo pairs.
// ---------------------------------------------------------------------------
__global__ __launch_bounds__(256) void split_w(
    const float* __restrict__ Wq, const float* __restrict__ Wk,
    const float* __restrict__ Wv)
{
    int idx = blockIdx.x * 256 + threadIdx.x;
    int which = idx >> 16;
    int i = idx & 65535;
    const float* W = (which == 0) ? Wq : (which == 1) ? Wk : Wv;
    u16 h, l;
    bfsplit(W[i], h, l);
    g_W1[which][i] = __ushort_as_bfloat16(h);
    g_W2[which][i] = __ushort_as_bfloat16(l);
}

// ---------------------------------------------------------------------------
// Kernel B: split + transpose x/attr -> [b][n][c] bf16 hi/lo.
// ---------------------------------------------------------------------------
__global__ __launch_bounds__(256) void split_x(
    const float* __restrict__ x, const float* __restrict__ attr)
{
    __shared__ float t[32][33];
    const int tid = threadIdx.x;
    const int b = blockIdx.z >> 1, ten = blockIdx.z & 1;
    const float* src = ten ? attr : x;
    __nv_bfloat16* d1 = ten ? g_Xa1 : g_Xx1;
    __nv_bfloat16* d2 = ten ? g_Xa2 : g_Xx2;
    const int n0 = blockIdx.x * 32, c0 = blockIdx.y * 32;

    {
        int r = tid >> 3, n4 = (tid & 7) * 4;
        float4 v = *(const float4*)(src + ((size_t)b * CDIM + c0 + r) * NSP + n0 + n4);
        t[r][n4 + 0] = v.x; t[r][n4 + 1] = v.y;
        t[r][n4 + 2] = v.z; t[r][n4 + 3] = v.w;
    }
    __syncthreads();
    {
        int nr = tid >> 3, c4 = (tid & 7) * 4;
        u16 h[4], l[4];
        #pragma unroll
        for (int k = 0; k < 4; k++) bfsplit(t[c4 + k][nr], h[k], l[k]);
        uint2 hw, lw;
        hw.x = (u32)h[0] | ((u32)h[1] << 16); hw.y = (u32)h[2] | ((u32)h[3] << 16);
        lw.x = (u32)l[0] | ((u32)l[1] << 16); lw.y = (u32)l[2] | ((u32)l[3] << 16);
        size_t base = ((size_t)b * NSP + n0 + nr) * CDIM + c0 + c4;
        *(uint2*)&d1[base] = hw;
        *(uint2*)&d2[base] = lw;
    }
}

// ---------------------------------------------------------------------------
// Kernel C: proj via mma (3-pass split bf16 core).  (unchanged)
// ---------------------------------------------------------------------------
#define PJ_X1 0
#define PJ_X2 33792
#define PJ_W  67584
#define PJ_ST 202752
#define PJ_B  220160
#define PJ_TOTAL 221184

__global__ __launch_bounds__(256, 1) void proj_mma(
    const float* __restrict__ bq, const float* __restrict__ bk,
    const float* __restrict__ bv)
{
    extern __shared__ __align__(16) char smem[];
    const u32 sb = smem_u32(smem);
    const int tid = threadIdx.x;
    const int lane = tid & 31, warp = tid >> 5;
    const int wr = warp >> 1, wc = warp & 1;
    const int gid = lane >> 2, tig = lane & 3;
    const int z = blockIdx.z, bb = blockIdx.y, n0 = blockIdx.x * 64;

    const __nv_bfloat16* xs1 = (z == 0) ? g_Xx1 : g_Xa1;
    const __nv_bfloat16* xs2 = (z == 0) ? g_Xx2 : g_Xa2;
    const __nv_bfloat16* w1 = g_W1[z];
    const __nv_bfloat16* w2 = g_W2[z];
    const float* bias = (z == 0) ? bq : (z == 1) ? bk : bv;

    float* bias_s = (float*)(smem + PJ_B);
    bias_s[tid] = bias[tid];

    #pragma unroll
    for (int it = 0; it < 8; it++) {
        int idx = it * 256 + tid;
        int j = idx >> 5, ch = idx & 31;
        size_t off = ((size_t)bb * NSP + n0 + j) * CDIM + ch * 8;
        CP16(sb + PJ_X1 + j * 528 + ch * 16, xs1 + off);
        CP16(sb + PJ_X2 + j * 528 + ch * 16, xs2 + off);
    }
    CPCOMMIT();

    auto issueW = [&](int oq) {
        u32 base = sb + PJ_W + (oq & 1) * 67584;
        #pragma unroll
        for (int it = 0; it < 8; it++) {
            int idx = it * 256 + tid;
            int o = idx >> 5, ch = idx & 31;
            size_t off = (size_t)(oq * 64 + o) * CDIM + ch * 8;
            CP16(base + o * 528 + ch * 16, w1 + off);
            CP16(base + 33792 + o * 528 + ch * 16, w2 + off);
        }
        CPCOMMIT();
    };
    issueW(0);

    const u32 aB1 = sb + PJ_X1 + (wr * 16 + (lane & 15)) * 528 + (lane >> 4) * 16;
    const u32 aB2 = sb + PJ_X2 + (wr * 16 + (lane & 15)) * 528 + (lane >> 4) * 16;
    const int bRow = wc * 32 + (lane & 7) + ((lane >> 4) << 3);
    const u32 bOffc = ((lane >> 3) & 1) * 16;

    for (int oq = 0; oq < 4; oq++) {
        CPWAIT(0);
        __syncthreads();
        if (oq < 3) issueW(oq + 1);

        u32 wbase = sb + PJ_W + (oq & 1) * 67584;
        u32 bB1 = wbase + bRow * 528 + bOffc;
        u32 bB2 = bB1 + 33792;

        float D[4][4];
        #pragma unroll
        for (int t = 0; t < 4; t++)
            #pragma unroll
            for (int e = 0; e < 4; e++) D[t][e] = 0.0f;

        #pragma unroll
        for (int kk = 0; kk < 16; kk++) {
            u32 a1[4], a2[4], bw1[8], bw2[8];
            ldsm4(a1, aB1 + kk * 32);
            ldsm4(a2, aB2 + kk * 32);
            ldsm4(bw1,     bB1 + kk * 32);
            ldsm4(bw1 + 4, bB1 + 16 * 528 + kk * 32);
            ldsm4(bw2,     bB2 + kk * 32);
            ldsm4(bw2 + 4, bB2 + 16 * 528 + kk * 32);
            #pragma unroll
            for (int t = 0; t < 4; t++) {
                mma_bf16(D[t], a1, bw1[2 * t], bw1[2 * t + 1]);
                mma_bf16(D[t], a1, bw2[2 * t], bw2[2 * t + 1]);
                mma_bf16(D[t], a2, bw1[2 * t], bw1[2 * t + 1]);
            }
        }

        if (z < 2) {
            __half* dst = (z == 0) ? g_Qh : g_Kh;
            const float sc = (z == 0) ? LOG2E : 1.0f;
            #pragma unroll
            for (int t = 0; t < 4; t++) {
                int o = oq * 64 + wc * 32 + t * 8 + 2 * tig;
                float b0 = bias_s[o], b1 = bias_s[o + 1];
                #pragma unroll
                for (int rh = 0; rh < 2; rh++) {
                    float f0 = (D[t][2 * rh + 0] + b0) * sc;
                    float f1 = (D[t][2 * rh + 1] + b1) * sc;
                    int n = n0 + wr * 16 + gid + rh * 8;
                    size_t idx = ((size_t)bb * NSP + n) * CDIM + o;
                    *(u32*)&dst[idx] = packh2(f0, f1);
                }
            }
        } else {
            float* st = (float*)(smem + PJ_ST);
            #pragma unroll
            for (int t = 0; t < 4; t++) {
                int ol = wc * 32 + t * 8 + 2 * tig;
                float b0 = bias_s[oq * 64 + ol], b1 = bias_s[oq * 64 + ol + 1];
                #pragma unroll
                for (int rh = 0; rh < 2; rh++) {
                    int nl = wr * 16 + gid + rh * 8;
                    st[ol * 68 + nl]       = D[t][2 * rh + 0] + b0;
                    st[(ol + 1) * 68 + nl] = D[t][2 * rh + 1] + b1;
                }
            }
            __syncthreads();
            int ol = tid >> 2, nch = (tid & 3) * 16;
            u32 hv[8];
            #pragma unroll
            for (int m = 0; m < 8; m++) {
                int s = nch + 2 * m;
                hv[m] = packh2(st[ol * 68 + s], st[ol * 68 + s + 1]);
            }
            __half* dst = g_Vh + ((size_t)bb * CDIM + oq * 64 + ol) * NSP + n0 + nch;
            *(uint4*)&dst[0] = make_uint4(hv[0], hv[1], hv[2], hv[3]);
            *(uint4*)&dst[8] = make_uint4(hv[4], hv[5], hv[6], hv[7]);
        }
    }
}

// ---------------------------------------------------------------------------
// Kernel D: bulk-synchronous warp-specialized flash attention.
// 384 threads, 1 CTA/SM.  Warps 0-3: S producers (16i x 32j).
// Warps 4-11: PV consumers (32i x 64c).  One __syncthreads per interval.
// FIX vs R16: group barrier AFTER each cp.async wait, BEFORE cross-warp reads
// (cp.async completion is only visible to other threads after a barrier).
// ---------------------------------------------------------------------------
#define SQ    0
#define SK0   33792       // 2 x 16896
#define SKSZ  16896
#define SV0   67584       // 2 x 20480
#define SVSZ  20480
#define SP0   108544      // 2 x 5120
#define SPSZ  5120
#define SRING 118784      // m ring [4][64] f32
#define SLR   119808
#define SM_TOTAL 120064
#define QK_STR 528
#define VH_STR 80
#define P_STR  80
#define OT_STR 258

__global__ __launch_bounds__(384, 1) void attn_kernel(
    const float* __restrict__ x, float* __restrict__ out)
{
    extern __shared__ __align__(16) char smem[];
    const u32 sb = smem_u32(smem);
    const int tid = threadIdx.x;
    const int lane = tid & 31;
    const int warp = tid >> 5;          // 0..11
    const int gid = lane >> 2, tig = lane & 3;
    const int bb = blockIdx.y;
    const int n0 = blockIdx.x * BQ;

    float* lrow = (float*)(smem + SLR);
    if (tid < 64) lrow[tid] = 0.0f;
    if (tid < 256) ((float*)(smem + SRING))[tid] = -1e30f;

    const __half* qg  = g_Qh + ((size_t)bb * NSP + n0) * CDIM;
    const __half* khg = g_Kh + (size_t)bb * NSP * CDIM;
    const __half* vhg = g_Vh + (size_t)bb * CDIM * NSP;

    // ---- Q tile (all 384 threads) ----
    #pragma unroll
    for (int it = 0; it < 6; it++) {
        int idx = it * 384 + tid;
        if (idx < 2048) {
            int i = idx >> 5, ch = idx & 31;
            uint4 v = *(const uint4*)&qg[(size_t)i * CDIM + ch * 8];
            sts_v4(sb + SQ + i * QK_STR + ch * 16, v);
        }
    }

    // ---- prefetch helpers ----
    auto issueK = [&](int kt) {           // S warps only (tid 0..127)
        int k0 = (kt & (NK - 1)) * BK;
        u32 base = sb + SK0 + (kt & 1) * SKSZ;
        #pragma unroll
        for (int it = 0; it < 8; it++) {
            int idx = it * 128 + tid;
            int j = idx >> 5, ch = idx & 31;
            CP16(base + j * QK_STR + ch * 16,
                 &khg[(size_t)(k0 + j) * CDIM + ch * 8]);
        }
        CPCOMMIT();
    };
    auto issueV = [&](int kt) {           // PV warps only (tid 128..383)
        int k0 = (kt & (NK - 1)) * BK;
        u32 base = sb + SV0 + (kt & 1) * SVSZ;
        int ptid = tid - 128;
        #pragma unroll
        for (int it = 0; it < 4; it++) {
            int idx = it * 256 + ptid;
            int c = idx >> 2, ch = idx & 3;
            CP16(base + c * VH_STR + ch * 16,
                 &vhg[(size_t)c * NSP + k0 + ch * 8]);
        }
        CPCOMMIT();
    };

    if (warp < 4) { issueK(0); issueK(1); }
    else          { issueV(0); issueV(1); }
    __syncthreads();

    // ---- persistent state ----
    const int i0s = (warp & 3) * 16;
    const int r0 = i0s + gid, r1 = r0 + 8;
    const u32 aBase = sb + SQ + (i0s + (lane & 15)) * QK_STR + (lane >> 4) * 16;
    const int bRow = (lane & 7) + ((lane >> 4) << 3);
    const u32 bOff = ((lane >> 3) & 1) * 16;
    float m0 = -1e30f, m1 = -1e30f, lsum0 = 0.0f, lsum1 = 0.0f;

    const int p = (warp >= 4) ? (warp - 4) : 0;
    const int wi = p >> 2, wcq = p & 3;
    const int i0p = wi * 32, c0q = wcq * 64;
    const u32 pldB = sb + SP0 + (i0p + (lane & 15)) * P_STR + (lane >> 4) * 16;
    const u32 vldB = sb + SV0 + (c0q + (lane & 7) + ((lane >> 4) << 3)) * VH_STR
                   + ((lane >> 3) & 1) * 16;
    float O[2][8][4];
    #pragma unroll
    for (int it = 0; it < 2; it++)
        #pragma unroll
        for (int nt = 0; nt < 8; nt++)
            #pragma unroll
            for (int e = 0; e < 4; e++) O[it][nt][e] = 0.0f;

    // ---- S-producer step: compute S(j), softmax -> P(j), ring[j] ----
    auto s_step = [&](int j) {
        CPWAIT(1);                        // my K(j) copies done
        BAR_SYNC(5, 128);                 // K(j) visible to ALL S warps
        const u32 bBase = sb + SK0 + (j & 1) * SKSZ + bRow * QK_STR + bOff;
        float S[4][4];
        #pragma unroll
        for (int t = 0; t < 4; t++)
            #pragma unroll
            for (int e = 0; e < 4; e++) S[t][e] = 0.0f;
        #pragma unroll
        for (int kk = 0; kk < 16; kk++) {
            u32 aq[4], b0[4], b1[4];
            ldsm4(aq, aBase + kk * 32);
            ldsm4(b0, bBase + kk * 32);
            ldsm4(b1, bBase + 16 * QK_STR + kk * 32);
            mma_f16(S[0], aq, b0[0], b0[1]);
            mma_f16(S[1], aq, b0[2], b0[3]);
            mma_f16(S[2], aq, b1[0], b1[1]);
            mma_f16(S[3], aq, b1[2], b1[3]);
        }
        BAR_SYNC(5, 128);                 // all S warps done reading K(j)
        issueK(j + 2);                    // overwrite buffer (j&1)

        float rm0 = fmaxf(fmaxf(S[0][0], S[0][1]), fmaxf(S[1][0], S[1][1]));
        rm0 = fmaxf(rm0, fmaxf(fmaxf(S[2][0], S[2][1]), fmaxf(S[3][0], S[3][1])));
        float rm1 = fmaxf(fmaxf(S[0][2], S[0][3]), fmaxf(S[1][2], S[1][3]));
        rm1 = fmaxf(rm1, fmaxf(fmaxf(S[2][2], S[2][3]), fmaxf(S[3][2], S[3][3])));
        rm0 = fmaxf(rm0, __shfl_xor_sync(0xffffffffu, rm0, 1));
        rm0 = fmaxf(rm0, __shfl_xor_sync(0xffffffffu, rm0, 2));
        rm1 = fmaxf(rm1, __shfl_xor_sync(0xffffffffu, rm1, 1));
        rm1 = fmaxf(rm1, __shfl_xor_sync(0xffffffffu, rm1, 2));
        float mn0 = fmaxf(m0, rm0);
        float mn1 = fmaxf(m1, rm1);
        lsum0 *= ex2f(m0 - mn0);
        lsum1 *= ex2f(m1 - mn1);
        if (tig == 0) {
            sts_f32(sb + SRING + ((j & 3) * 64 + r0) * 4, mn0);
            sts_f32(sb + SRING + ((j & 3) * 64 + r1) * 4, mn1);
        }
        m0 = mn0; m1 = mn1;

        u32 pbase = sb + SP0 + (j & 1) * SPSZ;
        #pragma unroll
        for (int t = 0; t < 4; t++) {
            int jc = t * 8 + 2 * tig;
            float p0 = ex2f(S[t][0] - mn0), p1 = ex2f(S[t][1] - mn0);
            float p2 = ex2f(S[t][2] - mn1), p3 = ex2f(S[t][3] - mn1);
            lsum0 += p0 + p1;
            lsum1 += p2 + p3;
            sts_u32(pbase + r0 * P_STR + jc * 2, packh2(p0, p1));
            sts_u32(pbase + r1 * P_STR + jc * 2, packh2(p2, p3));
        }
    };

    // ---- prologue interval: S(0) only ----
    if (warp < 4) s_step(0);
    __syncthreads();

    // ---- main loop: interval kt = S(kt+1) || PV(kt) ----
    for (int kt = 0; kt < NK; kt++) {
        if (warp < 4) {
            if (kt + 1 < NK) s_step(kt + 1);
        } else {
            CPWAIT(1);                    // my V(kt) copies done
            BAR_SYNC(6, 256);             // V(kt) visible to ALL PV warps
            // O rescale: m(kt-1) -> m(kt) from ring
            #pragma unroll
            for (int it = 0; it < 2; it++) {
                int r = i0p + it * 16 + gid;
                float mpa = lds_f32(sb + SRING + (((kt - 1) & 3) * 64 + r) * 4);
                float mpb = lds_f32(sb + SRING + (((kt - 1) & 3) * 64 + r + 8) * 4);
                float mna = lds_f32(sb + SRING + ((kt & 3) * 64 + r) * 4);
                float mnb = lds_f32(sb + SRING + ((kt & 3) * 64 + r + 8) * 4);
                if (mpa < mna || mpb < mnb) {
                    float sa = ex2f(mpa - mna), sbf = ex2f(mpb - mnb);
                    #pragma unroll
                    for (int nt = 0; nt < 8; nt++) {
                        O[it][nt][0] *= sa;  O[it][nt][1] *= sa;
                        O[it][nt][2] *= sbf; O[it][nt][3] *= sbf;
                    }
                }
            }
            const u32 pld = pldB + (kt & 1) * SPSZ;
            const u32 vld = vldB + (kt & 1) * SVSZ;
            #pragma unroll
            for (int ks = 0; ks < 2; ks++) {
                u32 a0[4], a1[4];
                ldsm4(a0, pld + ks * 32);
                ldsm4(a1, pld + 16 * P_STR + ks * 32);
                #pragma unroll
                for (int m = 0; m < 4; m++) {
                    u32 vb[4];
                    ldsm4(vb, vld + m * 16 * VH_STR + ks * 32);
                    mma_f16(O[0][2 * m],     a0, vb[0], vb[1]);
                    mma_f16(O[0][2 * m + 1], a0, vb[2], vb[3]);
                    mma_f16(O[1][2 * m],     a1, vb[0], vb[1]);
                    mma_f16(O[1][2 * m + 1], a1, vb[2], vb[3]);
                }
            }
            BAR_SYNC(6, 256);             // all PV warps done reading V(kt)
            issueV(kt + 2);               // overwrite buffer (kt&1)
        }
        __syncthreads();                  // interval handoff
    }

    // ---- drain + lrow ----
    CPWAIT(0);
    if (warp < 4) {
        lsum0 += __shfl_xor_sync(0xffffffffu, lsum0, 1);
        lsum0 += __shfl_xor_sync(0xffffffffu, lsum0, 2);
        lsum1 += __shfl_xor_sync(0xffffffffu, lsum1, 1);
        lsum1 += __shfl_xor_sync(0xffffffffu, lsum1, 2);
        if (tig == 0) {
            lrow[r0] = lsum0;
            lrow[r1] = lsum1;
        }
    }
    __syncthreads();

    // ---- transpose O through smem (PV warps; Q/K regions dead) ----
    if (warp >= 4) {
        #pragma unroll
        for (int it = 0; it < 2; it++)
            #pragma unroll
            for (int nt = 0; nt < 8; nt++) {
                int i = i0p + it * 16 + gid;
                int c = c0q + nt * 8 + 2 * tig;
                sts_v2f(sb + (i * OT_STR + c) * 4, O[it][nt][0], O[it][nt][1]);
                sts_v2f(sb + ((i + 8) * OT_STR + c) * 4, O[it][nt][2], O[it][nt][3]);
            }
    }
    __syncthreads();

    // ---- out = O/l + x (all 384 threads) ----
    const float* xb = x + (size_t)bb * CDIM * NSP;
    float* ob = out + (size_t)bb * CDIM * NSP;
    #pragma unroll 4
    for (int it = 0; it < 43; it++) {
        int idx = it * 384 + tid;
        if (idx < 16384) {
            int i = idx & 63, c = idx >> 6;
            float ov = lds_f32(sb + (i * OT_STR + c) * 4);
            size_t g = (size_t)c * NSP + n0 + i;
            ob[g] = ov / lrow[i] + xb[g];
        }
    }
}

// ---------------------------------------------------------------------------
extern "C" void kernel_launch(void* const* d_in, const int* in_sizes, int n_in,
                              void* d_out, int out_size)
{
    const float* x    = (const float*)d_in[0];
    const float* attr = (const float*)d_in[1];
    const float* Wq   = (const float*)d_in[2];
    const float* bq   = (const float*)d_in[3];
    const float* Wk   = (const float*)d_in[4];
    const float* bk   = (const float*)d_in[5];
    const float* Wv   = (const float*)d_in[6];
    const float* bv   = (const float*)d_in[7];
    float* out = (float*)d_out;

    cudaFuncSetAttribute(proj_mma,
                         cudaFuncAttributeMaxDynamicSharedMemorySize, PJ_TOTAL);
    cudaFuncSetAttribute(attn_kernel,
                         cudaFuncAttributeMaxDynamicSharedMemorySize, SM_TOTAL);

    split_w<<<768, 256>>>(Wq, Wk, Wv);
    split_x<<<dim3(NSP / 32, CDIM / 32, NB * 2), 256>>>(x, attr);
    proj_mma<<<dim3(NSP / 64, NB, 3), 256, PJ_TOTAL>>>(bq, bk, bv);
    attn_kernel<<<dim3(NSP / BQ, NB), 384, SM_TOTAL>>>(x, out);
}